// round 6
// baseline (speedup 1.0000x reference)
#include <cuda_runtime.h>
#include <cuda_bf16.h>
#include <cstdint>

// ---------------- problem constants ----------------
#define NB     65536
#define GS     7
#define INH    5
#define GH     144
#define LINH   128
#define MTOT   (NB*GS)        // 458752 rows
#define MT     112            // rows per CTA = 16 whole graphs
#define NCTA   (MTOT/MT)      // 4096
#define NWARP  14
#define NTHR   (NWARP*32)     // 448
#define KT     9              // 144/16 k-tiles
#define NT     18             // 144/8 n-tiles per warp
#define HS     292            // smem h row stride (pad vs 288)
#define ABLK   1024           // bytes per (mtile,ktile) frag block
#define AMT    (KT*ABLK)      // 9216 bytes per mtile
#define BBLK   512            // bytes per (ktile,ntile) frag block
#define BSLOT  (KT*NT*BBLK)   // 82944 bytes per weight slot
#define NITEM  (16*72)        // epilogue items: 16 graphs x 72 col-pairs

// ---------------- device scratch ----------------
__device__ float g_adjn[(size_t)NB*GS*GS];
__device__ float g_adji[(size_t)NB*GS*GS];
__device__ unsigned char g_X[(size_t)(MTOT/16)*AMT];   // frag-packed hi|lo bf16
__device__ unsigned char g_B[4*BSLOT];
__device__ float g_v[GH];

// ---------------- helpers ----------------
__device__ __forceinline__ uint32_t pack_bf16(float a, float b) {
    __nv_bfloat162 t = __floats2bfloat162_rn(a, b);
    return *(uint32_t*)&t;
}
__device__ __forceinline__ void hilo(float x, float& hi, float& lo) {
    hi = __bfloat162float(__float2bfloat16(x));
    lo = x - hi;
}
__device__ __forceinline__ void mma_bf16(float* c, uint32_t a0, uint32_t a1,
                                         uint32_t a2, uint32_t a3,
                                         uint32_t b0, uint32_t b1) {
    asm volatile(
        "mma.sync.aligned.m16n8k16.row.col.f32.bf16.bf16.f32 "
        "{%0,%1,%2,%3}, {%4,%5,%6,%7}, {%8,%9}, {%0,%1,%2,%3};"
        : "+f"(c[0]), "+f"(c[1]), "+f"(c[2]), "+f"(c[3])
        : "r"(a0), "r"(a1), "r"(a2), "r"(a3), "r"(b0), "r"(b1));
}

// ---------------- shared memory layout ----------------
struct SMem {
    float h[MT*HS];        // 130816 B: 112 x [h1 | h2] fp32
    float adjn[16*49];
    float adji[16*49];
    float gsum[16];
    float v[GH];
    union {
        float extra[2048];   // k_L0: ops(560) w1(720) w2(720)
        uint4 sB[1152];      // k_gemmix: B stage, 2 slots x 576 uint4 per kt
    } u;
};
#define SMEMB ((int)sizeof(SMem))

// ================= kernel 1: adjacency prep ====================================
__global__ void k_prep(const float* __restrict__ adj) {
    __shared__ float s[128*49];
    const int tid = threadIdx.x;
    const size_t base = (size_t)blockIdx.x * 128 * 49;

    for (int i = tid; i < 128*49; i += 128) s[i] = adj[base + i];
    __syncthreads();
    float a[49];
#pragma unroll
    for (int i = 0; i < 49; i++) a[i] = s[tid*49 + i];
    __syncthreads();

#pragma unroll
    for (int i = 0; i < 7; i++) {
        a[i*7 + i] += 1.0f;
        float rs = 0.f;
#pragma unroll
        for (int j = 0; j < 7; j++) rs += a[i*7 + j];
        const float inv = 1.0f / rs;
#pragma unroll
        for (int j = 0; j < 7; j++) a[i*7 + j] *= inv;
    }
#pragma unroll
    for (int i = 0; i < 7; i++) {
        float rs = 0.f;
#pragma unroll
        for (int j = 0; j < 7; j++) rs += a[i*7 + j];
        const float inv = 1.0f / rs;
#pragma unroll
        for (int j = 0; j < 7; j++) s[tid*49 + i*7 + j] = a[i*7 + j] * inv;
    }
    __syncthreads();
    for (int i = tid; i < 128*49; i += 128) g_adjn[base + i] = s[i];
    __syncthreads();
#pragma unroll
    for (int i = 0; i < 7; i++) {
        float cs = 0.f;
#pragma unroll
        for (int r = 0; r < 7; r++) cs += a[r*7 + i];
        const float inv = 1.0f / cs;
#pragma unroll
        for (int j = 0; j < 7; j++) s[tid*49 + i*7 + j] = a[j*7 + i] * inv;
    }
    __syncthreads();
    for (int i = tid; i < 128*49; i += 128) g_adji[base + i] = s[i];
}

// ================= kernel 2: v = fc1^T fc2 ====================================
__global__ void k_v(const float* __restrict__ fc1, const float* __restrict__ fc2) {
    const int k = threadIdx.x;
    if (k < GH) {
        float s = 0.f;
        for (int j = 0; j < LINH; j++) s = fmaf(fc2[j], fc1[j*GH + k], s);
        g_v[k] = s;
    }
}

// ================= kernel 3: pack weights into B fragments ====================
__global__ void k_bprep(const float* __restrict__ a, const float* __restrict__ b,
                        const float* __restrict__ c, const float* __restrict__ d) {
    const float* W = blockIdx.x == 0 ? a : blockIdx.x == 1 ? b
                   : blockIdx.x == 2 ? c : d;
    unsigned char* out = g_B + (size_t)blockIdx.x * BSLOT;
    for (int f = threadIdx.x; f < KT*NT*32; f += 256) {
        const int kt = f / (NT*32);
        const int nt = (f / 32) % NT;
        const int l  = f & 31;
        const int n  = nt*8 + (l >> 2);
        const int kb = kt*16 + (l & 3)*2;
        float w0 = W[(kb+0)*GH + n], w1 = W[(kb+1)*GH + n];
        float w8 = W[(kb+8)*GH + n], w9 = W[(kb+9)*GH + n];
        float h0,l0,h1,l1,h8,l8,h9,l9;
        hilo(w0,h0,l0); hilo(w1,h1,l1); hilo(w8,h8,l8); hilo(w9,h9,l9);
        uint4 v;
        v.x = pack_bf16(h0,h1); v.y = pack_bf16(h8,h9);
        v.z = pack_bf16(l0,l1); v.w = pack_bf16(l8,l9);
        *(uint4*)(out + (size_t)(kt*NT + nt)*BBLK + l*16) = v;
    }
}

// ================= restructured mix epilogue ===================================
// Item = (graph g, column-pair kp). Loads h columns ONCE per item (float2),
// computes all 7 rows; writes frag-packed g_X or accumulates pooled dot with v.
template <bool FINAL>
__device__ void mix_epilogue(SMem* s, int cta, const float* __restrict__ nv,
                             float* __restrict__ out) {
    const int tid = threadIdx.x;
    if (FINAL) {
        if (tid < 16) s->gsum[tid] = 0.f;
        if (tid < GH) s->v[tid] = g_v[tid];
    }
    __syncthreads();   // h complete (+ gsum/v init)

    for (int item = tid; item < NITEM; item += NTHR) {
        const int g  = item / 72;
        const int kp = item - g*72;
        const int k0 = kp*2;

        float h1a[7], h1b[7], h2a[7], h2b[7];
        const float* hb = &s->h[(g*7)*HS];
#pragma unroll
        for (int j = 0; j < 7; j++) {
            const float2 t1 = *(const float2*)&hb[j*HS + k0];
            const float2 t2 = *(const float2*)&hb[j*HS + GH + k0];
            h1a[j] = t1.x; h1b[j] = t1.y;
            h2a[j] = t2.x; h2b[j] = t2.y;
        }
        const float* an = &s->adjn[g*49];
        const float* ai = &s->adji[g*49];

        float cs0 = 0.f, cs1 = 0.f;
#pragma unroll
        for (int i = 0; i < 7; i++) {
            float o1a = 0.f, o1b = 0.f, o2a = 0.f, o2b = 0.f;
#pragma unroll
            for (int j = 0; j < 7; j++) {
                const float wn = an[i*7 + j], wi = ai[i*7 + j];
                o1a = fmaf(wn, h1a[j], o1a); o1b = fmaf(wn, h1b[j], o1b);
                o2a = fmaf(wi, h2a[j], o2a); o2b = fmaf(wi, h2b[j], o2b);
            }
            const float x0 = 0.5f * (fmaxf(o1a, 0.f) + fmaxf(o2a, 0.f));
            const float x1 = 0.5f * (fmaxf(o1b, 0.f) + fmaxf(o2b, 0.f));

            if (!FINAL) {
                float hi0, lo0, hi1, lo1;
                hilo(x0, hi0, lo0); hilo(x1, hi1, lo1);
                const int r  = g*7 + i;
                const int mtile = r >> 4, rt = r & 15;
                const int kt = kp >> 3, c2 = kp & 7;
                const int l  = (rt & 7)*4 + (c2 & 3);
                const int w  = (rt >> 3) + 2*(c2 >> 2);
                uint32_t* base = (uint32_t*)(g_X +
                    ((size_t)(cta*7 + mtile)*KT + kt)*ABLK);
                base[l*8 + w]     = pack_bf16(hi0, hi1);
                base[l*8 + 4 + w] = pack_bf16(lo0, lo1);
            } else {
                cs0 += x0; cs1 += x1;
            }
        }
        if (FINAL)
            atomicAdd(&s->gsum[g], cs0 * s->v[k0] + cs1 * s->v[k0+1]);
    }

    if (FINAL) {
        __syncthreads();
        if (tid < 16) {
            const int b = cta*16 + tid;
            out[b] = s->gsum[tid] / nv[b];
        }
    }
}

__device__ __forceinline__ void load_adj(SMem* s, int cta) {
    for (int i = threadIdx.x; i < 16*49; i += NTHR) {
        s->adjn[i] = g_adjn[(size_t)cta*784 + i];
        s->adji[i] = g_adji[(size_t)cta*784 + i];
    }
}

// ================= kernel 4: layer 0 (fp32 K=5 GEMM) + mix -> frag X ==========
__global__ void __launch_bounds__(NTHR, 1)
k_L0(const float* __restrict__ ops, const float* __restrict__ w1,
     const float* __restrict__ w2) {
    extern __shared__ unsigned char smraw[];
    SMem* s = (SMem*)smraw;
    const int cta = blockIdx.x, tid = threadIdx.x;

    load_adj(s, cta);
    for (int q = tid; q < 560; q += NTHR) s->u.extra[q] = ops[(size_t)cta*560 + q];
    for (int q = tid; q < 720; q += NTHR) {
        s->u.extra[560  + q] = w1[q];
        s->u.extra[1280 + q] = w2[q];
    }
    __syncthreads();

    for (int idx = tid; idx < MT*288; idx += NTHR) {
        const int i = idx / 288, c = idx - i*288;
        const int k = (c < GH) ? c : c - GH;
        const float* W  = &s->u.extra[560 + (c < GH ? 0 : 720) + k];
        const float* xi = &s->u.extra[i*5];
        float h = 0.f;
#pragma unroll
        for (int t = 0; t < INH; t++) h = fmaf(xi[t], W[t*GH], h);
        s->h[i*HS + c] = h;
    }
    mix_epilogue<false>(s, cta, nullptr, nullptr);
}

// ================= kernel 5: fused HMMA GEMM + mix (B staged in smem) =========
__device__ __forceinline__ uint4 fetchB(const uint4* B0, const uint4* B1,
                                        int kt, int idx) {
    return (idx < 576) ? B0[kt*576 + idx] : B1[kt*576 + (idx - 576)];
}

__global__ void __launch_bounds__(NTHR, 1)
k_gemmix(int slot0, int is_final, const float* __restrict__ nv,
         float* __restrict__ out) {
    extern __shared__ unsigned char smraw[];
    SMem* s = (SMem*)smraw;
    const int cta = blockIdx.x, tid = threadIdx.x;
    const int wid = tid >> 5, lane = tid & 31;
    const int wr = wid % 7, wc = wid / 7;

    load_adj(s, cta);

    const uint4* __restrict__ Ab = (const uint4*)(g_X + (size_t)(cta*7 + wr)*AMT);
    const uint4* __restrict__ B0 = (const uint4*)(g_B + (size_t)slot0*BSLOT);
    const uint4* __restrict__ B1 = B0 + BSLOT/16;

    float acc[NT][4];
#pragma unroll
    for (int t = 0; t < NT; t++)
#pragma unroll
        for (int q = 0; q < 4; q++) acc[t][q] = 0.f;

    const bool has2 = (tid < 1152 - 2*NTHR);   // tid < 256
    uint4 bp0 = fetchB(B0, B1, 0, tid);
    uint4 bp1 = fetchB(B0, B1, 0, tid + NTHR);
    uint4 bp2 = has2 ? fetchB(B0, B1, 0, tid + 2*NTHR) : make_uint4(0,0,0,0);
    uint4 ah = Ab[lane*2], al = Ab[lane*2 + 1];

#pragma unroll
    for (int kt = 0; kt < KT; kt++) {
        s->u.sB[tid]        = bp0;
        s->u.sB[tid + NTHR] = bp1;
        if (has2) s->u.sB[tid + 2*NTHR] = bp2;
        __syncthreads();

        const uint4 ahc = ah, alc = al;
        if (kt + 1 < KT) {
            bp0 = fetchB(B0, B1, kt+1, tid);
            bp1 = fetchB(B0, B1, kt+1, tid + NTHR);
            if (has2) bp2 = fetchB(B0, B1, kt+1, tid + 2*NTHR);
            ah = Ab[(kt+1)*64 + lane*2];
            al = Ab[(kt+1)*64 + lane*2 + 1];
        }

        const uint4* bw = &s->u.sB[wc*576];
#pragma unroll
        for (int nt = 0; nt < NT; nt++) {
            const uint4 b = bw[nt*32 + lane];
            mma_bf16(acc[nt], ahc.x, ahc.y, ahc.z, ahc.w, b.x, b.y);  // hi*hi
            mma_bf16(acc[nt], ahc.x, ahc.y, ahc.z, ahc.w, b.z, b.w);  // hi*lo
            mma_bf16(acc[nt], alc.x, alc.y, alc.z, alc.w, b.x, b.y);  // lo*hi
        }
        __syncthreads();
    }

    // stage results: rows wr*16 + l/4 (+8), cols wc*144 + nt*8 + (l%4)*2
    const int row0 = wr*16 + (lane >> 2);
    const int colb = wc*GH + (lane & 3)*2;
#pragma unroll
    for (int nt = 0; nt < NT; nt++) {
        const int col = colb + nt*8;
        s->h[row0*HS + col]       = acc[nt][0];
        s->h[row0*HS + col + 1]   = acc[nt][1];
        s->h[(row0+8)*HS + col]   = acc[nt][2];
        s->h[(row0+8)*HS + col+1] = acc[nt][3];
    }

    if (is_final) mix_epilogue<true>(s, cta, nv, out);
    else          mix_epilogue<false>(s, cta, nullptr, nullptr);
}

// ================= launch ======================================================
extern "C" void kernel_launch(void* const* d_in, const int* in_sizes, int n_in,
                              void* d_out, int out_size) {
    const float* ops  = (const float*)d_in[0];
    const float* adj  = (const float*)d_in[1];
    const float* nv   = (const float*)d_in[2];
    const float* w1_0 = (const float*)d_in[3];
    const float* w2_0 = (const float*)d_in[4];
    const float* w1_1 = (const float*)d_in[5];
    const float* w2_1 = (const float*)d_in[6];
    const float* w1_2 = (const float*)d_in[7];
    const float* w2_2 = (const float*)d_in[8];
    const float* fc1  = (const float*)d_in[9];
    const float* fc2  = (const float*)d_in[10];
    float* out = (float*)d_out;

    static int configured = 0;
    if (!configured) {
        cudaFuncSetAttribute(k_L0,     cudaFuncAttributeMaxDynamicSharedMemorySize, SMEMB);
        cudaFuncSetAttribute(k_gemmix, cudaFuncAttributeMaxDynamicSharedMemorySize, SMEMB);
        configured = 1;
    }

    k_prep <<<NB/128, 128>>>(adj);
    k_v    <<<1, GH>>>(fc1, fc2);
    k_bprep<<<4, 256>>>(w1_1, w2_1, w1_2, w2_2);
    k_L0   <<<NCTA, NTHR, SMEMB>>>(ops, w1_0, w2_0);
    k_gemmix<<<NCTA, NTHR, SMEMB>>>(0, 0, nv, out);   // layer 1
    k_gemmix<<<NCTA, NTHR, SMEMB>>>(2, 1, nv, out);   // layer 2 + pool + fc
}

// round 7
// speedup vs baseline: 1.3050x; 1.3050x over previous
#include <cuda_runtime.h>
#include <cuda_bf16.h>
#include <cstdint>

// ---------------- problem constants ----------------
#define NB     65536
#define GS     7
#define INH    5
#define GH     144
#define LINH   128
#define GPC    4              // graphs per CTA (padded to 8 rows each)
#define NCTA   (NB/GPC)       // 16384
#define NTHR   128            // 4 warps: (mtile 0..1) x (slot 0..1)
#define KT     9              // 144/16 k-tiles
#define NT     18             // 144/8 n-tiles (full N per warp)
#define HS2    290            // sH row stride (floats, even, mod32=2)
#define BBLK   512            // bytes per (ktile,ntile) B frag block
#define BSLOT  (KT*NT*BBLK)   // 82944 bytes per weight slot

// ---------------- device scratch ----------------
__device__ unsigned char g_B[4*BSLOT];   // frag-packed split-bf16 weights
__device__ float g_v[GH];                // fused fc vector

// ---------------- helpers ----------------
__device__ __forceinline__ uint32_t pack_bf16(float a, float b) {
    __nv_bfloat162 t = __floats2bfloat162_rn(a, b);
    return *(uint32_t*)&t;
}
__device__ __forceinline__ void hilo(float x, float& hi, float& lo) {
    hi = __bfloat162float(__float2bfloat16(x));
    lo = x - hi;
}
__device__ __forceinline__ void mma_bf16(float* c, uint32_t a0, uint32_t a1,
                                         uint32_t a2, uint32_t a3,
                                         uint32_t b0, uint32_t b1) {
    asm volatile(
        "mma.sync.aligned.m16n8k16.row.col.f32.bf16.bf16.f32 "
        "{%0,%1,%2,%3}, {%4,%5,%6,%7}, {%8,%9}, {%0,%1,%2,%3};"
        : "+f"(c[0]), "+f"(c[1]), "+f"(c[2]), "+f"(c[3])
        : "r"(a0), "r"(a1), "r"(a2), "r"(a3), "r"(b0), "r"(b1));
}

// ---------------- shared memory ----------------
struct SM {
    float h[32*HS2];            // 37120 B: 32 rows x [h1(144) | h2(144)] fp32
    union {
        uint4 sX[2*KT*64];      // 18432 B: frag-packed split-bf16 X (2 mtiles)
        struct { float ops[GPC*35]; float w0[2*720]; } l0;
    } u;
    float adjn[GPC*49];
    float adji[GPC*49];
    float adjraw[GPC*49];
    float v[GH];
    float gsum[GPC];
};
#define SMEMB ((int)sizeof(SM))

// ================= kernel: v = fc1^T fc2 ======================================
__global__ void k_v(const float* __restrict__ fc1, const float* __restrict__ fc2) {
    const int k = threadIdx.x;
    if (k < GH) {
        float s = 0.f;
        for (int j = 0; j < LINH; j++) s = fmaf(fc2[j], fc1[j*GH + k], s);
        g_v[k] = s;
    }
}

// ================= kernel: pack weights into B fragments ======================
// slot order: 0=w1_1 1=w2_1 2=w1_2 3=w2_2.  B frag (proven in R5).
__global__ void k_bprep(const float* __restrict__ a, const float* __restrict__ b,
                        const float* __restrict__ c, const float* __restrict__ d) {
    const float* W = blockIdx.x == 0 ? a : blockIdx.x == 1 ? b
                   : blockIdx.x == 2 ? c : d;
    unsigned char* out = g_B + (size_t)blockIdx.x * BSLOT;
    for (int f = threadIdx.x; f < KT*NT*32; f += 256) {
        const int kt = f / (NT*32);
        const int nt = (f / 32) % NT;
        const int l  = f & 31;
        const int n  = nt*8 + (l >> 2);
        const int kb = kt*16 + (l & 3)*2;
        float w0 = W[(kb+0)*GH + n], w1 = W[(kb+1)*GH + n];
        float w8 = W[(kb+8)*GH + n], w9 = W[(kb+9)*GH + n];
        float h0,l0,h1,l1,h8,l8,h9,l9;
        hilo(w0,h0,l0); hilo(w1,h1,l1); hilo(w8,h8,l8); hilo(w9,h9,l9);
        uint4 v;
        v.x = pack_bf16(h0,h1); v.y = pack_bf16(h8,h9);
        v.z = pack_bf16(l0,l1); v.w = pack_bf16(l8,l9);
        *(uint4*)(out + (size_t)(kt*NT + nt)*BBLK + l*16) = v;
    }
}

// ================= per-graph adjacency prep (one thread per graph) ============
__device__ void prep_graph(SM* s, int g) {
    float a[49];
#pragma unroll
    for (int i = 0; i < 49; i++) a[i] = s->adjraw[g*49 + i];
    // adj_d = rownorm(adj + I)
#pragma unroll
    for (int i = 0; i < 7; i++) {
        a[i*7 + i] += 1.0f;
        float rs = 0.f;
#pragma unroll
        for (int j = 0; j < 7; j++) rs += a[i*7 + j];
        const float inv = 1.0f / rs;
#pragma unroll
        for (int j = 0; j < 7; j++) a[i*7 + j] *= inv;
    }
    // norm_adj = rownorm(adj_d)
#pragma unroll
    for (int i = 0; i < 7; i++) {
        float rs = 0.f;
#pragma unroll
        for (int j = 0; j < 7; j++) rs += a[i*7 + j];
        const float inv = 1.0f / rs;
#pragma unroll
        for (int j = 0; j < 7; j++) s->adjn[g*49 + i*7 + j] = a[i*7 + j] * inv;
    }
    // inv_norm_adj[i][j] = adj_d[j][i] / colsum_i(adj_d)
#pragma unroll
    for (int i = 0; i < 7; i++) {
        float cs = 0.f;
#pragma unroll
        for (int r = 0; r < 7; r++) cs += a[r*7 + i];
        const float inv = 1.0f / cs;
#pragma unroll
        for (int j = 0; j < 7; j++) s->adji[g*49 + i*7 + j] = a[j*7 + i] * inv;
    }
}

// ================= mix: sH -> (sX frags | pooled gsum) ========================
template <bool FINAL>
__device__ void mix(SM* s) {
    const int tid = threadIdx.x;
    __syncthreads();   // sH complete; all sX reads done

    for (int item = tid; item < GPC*72; item += NTHR) {
        const int g  = item / 72;
        const int kp = item - g*72;
        const int k0 = kp*2;

        float h1a[7], h1b[7], h2a[7], h2b[7];
#pragma unroll
        for (int j = 0; j < 7; j++) {
            const float2 t1 = *(const float2*)&s->h[(g*8+j)*HS2 + k0];
            const float2 t2 = *(const float2*)&s->h[(g*8+j)*HS2 + GH + k0];
            h1a[j] = t1.x; h1b[j] = t1.y;
            h2a[j] = t2.x; h2b[j] = t2.y;
        }
        const float* an = &s->adjn[g*49];
        const float* ai = &s->adji[g*49];

        const int mt = g >> 1;
        const int kt = k0 >> 4, c2 = (k0 & 15) >> 1;
        uint32_t* X = (uint32_t*)s->u.sX;
        const int base = (mt*KT + kt)*256;
        const int wsel = (g & 1) + 2*(c2 >> 2);

        float cs0 = 0.f, cs1 = 0.f;
#pragma unroll
        for (int i = 0; i < 7; i++) {
            float o1a = 0.f, o1b = 0.f, o2a = 0.f, o2b = 0.f;
#pragma unroll
            for (int j = 0; j < 7; j++) {
                const float wn = an[i*7 + j], wi = ai[i*7 + j];
                o1a = fmaf(wn, h1a[j], o1a); o1b = fmaf(wn, h1b[j], o1b);
                o2a = fmaf(wi, h2a[j], o2a); o2b = fmaf(wi, h2b[j], o2b);
            }
            const float x0 = 0.5f * (fmaxf(o1a, 0.f) + fmaxf(o2a, 0.f));
            const float x1 = 0.5f * (fmaxf(o1b, 0.f) + fmaxf(o2b, 0.f));

            if (!FINAL) {
                float hi0, lo0, hi1, lo1;
                hilo(x0, hi0, lo0); hilo(x1, hi1, lo1);
                const int l = i*4 + (c2 & 3);
                X[base + l*4 + wsel]       = pack_bf16(hi0, hi1);
                X[base + 128 + l*4 + wsel] = pack_bf16(lo0, lo1);
            } else {
                cs0 += x0; cs1 += x1;
            }
        }
        if (FINAL)
            atomicAdd(&s->gsum[g], cs0 * s->v[k0] + cs1 * s->v[k0+1]);
    }
    __syncthreads();   // sX/gsum complete before next phase
}

// ================= GEMM: sX (frags) x g_B[slot] -> sH =========================
__device__ void gemm(SM* s, int mt, int sl, int slot) {
    const int lane = threadIdx.x & 31;
    const uint4* __restrict__ Bp = (const uint4*)(g_B + (size_t)slot*BSLOT);
    const uint4* Xv = s->u.sX;

    float acc[NT][4];
#pragma unroll
    for (int t = 0; t < NT; t++)
#pragma unroll
        for (int q = 0; q < 4; q++) acc[t][q] = 0.f;

#pragma unroll
    for (int kt = 0; kt < KT; kt++) {
        const uint4 ah = Xv[(mt*KT + kt)*64 + lane];
        const uint4 al = Xv[(mt*KT + kt)*64 + 32 + lane];
#pragma unroll
        for (int nt = 0; nt < NT; nt++) {
            const uint4 b = Bp[(kt*NT + nt)*32 + lane];
            mma_bf16(acc[nt], ah.x, ah.y, ah.z, ah.w, b.x, b.y);  // hi*hi
            mma_bf16(acc[nt], ah.x, ah.y, ah.z, ah.w, b.z, b.w);  // hi*lo
            mma_bf16(acc[nt], al.x, al.y, al.z, al.w, b.x, b.y);  // lo*hi
        }
    }

    const int r0 = mt*16 + (lane >> 2);
    const int c0 = sl*GH + (lane & 3)*2;
#pragma unroll
    for (int nt = 0; nt < NT; nt++) {
        *(float2*)&s->h[r0*HS2 + c0 + nt*8]     = make_float2(acc[nt][0], acc[nt][1]);
        *(float2*)&s->h[(r0+8)*HS2 + c0 + nt*8] = make_float2(acc[nt][2], acc[nt][3]);
    }
}

// ================= the fused kernel ===========================================
__global__ void __launch_bounds__(NTHR, 3)
k_fused(const float* __restrict__ ops, const float* __restrict__ adj,
        const float* __restrict__ nv,
        const float* __restrict__ w1_0, const float* __restrict__ w2_0,
        float* __restrict__ out) {
    extern __shared__ unsigned char smraw[];
    SM* s = (SM*)smraw;
    const int cta = blockIdx.x, tid = threadIdx.x;
    const int warp = tid >> 5, lane = tid & 31;
    const int mt = warp >> 1, sl = warp & 1;

    // ---- cooperative loads ----
    for (int q = tid; q < GPC*35; q += NTHR) s->u.l0.ops[q] = ops[(size_t)cta*GPC*35 + q];
    for (int q = tid; q < 720; q += NTHR) {
        s->u.l0.w0[q]       = w1_0[q];
        s->u.l0.w0[720 + q] = w2_0[q];
    }
    for (int q = tid; q < GH; q += NTHR)     s->v[q] = g_v[q];
    for (int q = tid; q < GPC*49; q += NTHR) s->adjraw[q] = adj[(size_t)cta*GPC*49 + q];
    if (tid < GPC) s->gsum[tid] = 0.f;
    __syncthreads();

    // ---- adjacency prep (one thread per graph) ----
    if (tid < GPC) prep_graph(s, tid);

    // ---- layer 0: h = ops @ W (K=5) in frag positions ----
    {
        const int r0 = lane >> 2;          // 0..7 (row within graph; 7 = pad)
        const int g0 = 2*mt, g1 = 2*mt + 1;
        const float* W = &s->u.l0.w0[sl*720];
        float o0[INH], o1[INH];
#pragma unroll
        for (int t = 0; t < INH; t++) {
            o0[t] = (r0 < 7) ? s->u.l0.ops[g0*35 + r0*5 + t] : 0.f;
            o1[t] = (r0 < 7) ? s->u.l0.ops[g1*35 + r0*5 + t] : 0.f;
        }
        const int rr = mt*16 + r0;
        const int cb = sl*GH + (lane & 3)*2;
#pragma unroll
        for (int nt = 0; nt < NT; nt++) {
            const int c = nt*8 + (lane & 3)*2;
            float h00 = 0.f, h01 = 0.f, h10 = 0.f, h11 = 0.f;
#pragma unroll
            for (int t = 0; t < INH; t++) {
                const float wa = W[t*GH + c], wb = W[t*GH + c + 1];
                h00 = fmaf(o0[t], wa, h00); h01 = fmaf(o0[t], wb, h01);
                h10 = fmaf(o1[t], wa, h10); h11 = fmaf(o1[t], wb, h11);
            }
            *(float2*)&s->h[rr*HS2 + cb + nt*8]     = make_float2(h00, h01);
            *(float2*)&s->h[(rr+8)*HS2 + cb + nt*8] = make_float2(h10, h11);
        }
    }
    mix<false>(s);                 // L0 mix -> sX (X1 frags)

    gemm(s, mt, sl, 0 + sl);       // layer 1: slots {w1_1, w2_1}
    mix<false>(s);                 // -> sX (X2 frags)

    gemm(s, mt, sl, 2 + sl);       // layer 2: slots {w1_2, w2_2}
    mix<true>(s);                  // -> gsum (pool . v)

    if (tid < GPC) {
        const int b = cta*GPC + tid;
        out[b] = s->gsum[tid] / nv[b];
    }
}

// ================= launch ======================================================
extern "C" void kernel_launch(void* const* d_in, const int* in_sizes, int n_in,
                              void* d_out, int out_size) {
    const float* ops  = (const float*)d_in[0];
    const float* adj  = (const float*)d_in[1];
    const float* nv   = (const float*)d_in[2];
    const float* w1_0 = (const float*)d_in[3];
    const float* w2_0 = (const float*)d_in[4];
    const float* w1_1 = (const float*)d_in[5];
    const float* w2_1 = (const float*)d_in[6];
    const float* w1_2 = (const float*)d_in[7];
    const float* w2_2 = (const float*)d_in[8];
    const float* fc1  = (const float*)d_in[9];
    const float* fc2  = (const float*)d_in[10];
    float* out = (float*)d_out;

    static int configured = 0;
    if (!configured) {
        cudaFuncSetAttribute(k_fused, cudaFuncAttributeMaxDynamicSharedMemorySize, SMEMB);
        configured = 1;
    }

    k_v    <<<1, GH>>>(fc1, fc2);
    k_bprep<<<4, 256>>>(w1_1, w2_1, w1_2, w2_2);
    k_fused<<<NCTA, NTHR, SMEMB>>>(ops, adj, nv, w1_0, w2_0, out);
}